// round 4
// baseline (speedup 1.0000x reference)
#include <cuda_runtime.h>
#include <cuda_bf16.h>
#include <cstdint>

#define BN 128
#define HN 512
#define EN 256
#define VN 50000
#define SN 200
#define KT 1792     // 3H + E
#define GIN 1280    // 2H + E

// ---------------- device scratch (allocation-free rule: __device__ globals) ----
__device__ float g_u2p[32 * 1024];
__device__ float g_u2[1024];
__device__ float g_to[BN * KT];               // to_out = [h_new | context | emb_x]
__device__ __align__(16) __nv_bfloat16 g_ahi[BN * KT];
__device__ __align__(16) __nv_bfloat16 g_alo[BN * KT];

#define SWZ128(o) ((o) ^ (((o) >> 3) & 0x70))

// ---------------- kernel 1: emb gather into to_out[:, 1536:1792] ---------------
__global__ void k_emb(const int* __restrict__ x, const float* __restrict__ emb) {
    int b = blockIdx.x;
    g_to[b * KT + 1536 + threadIdx.x] = emb[(size_t)x[b] * EN + threadIdx.x];
}

// ---------------- kernel 2/3: u2 = attn_w[:, H:3H].T @ v (partial + reduce) ----
__global__ void k_u2p(const float* __restrict__ aw, const float* __restrict__ v) {
    int g = blockIdx.x;  // h-range [g*16, g*16+16)
    for (int jj = 0; jj < 4; jj++) {
        int j = threadIdx.x + jj * 256;
        float acc = 0.f;
#pragma unroll
        for (int h = 0; h < 16; h++) {
            int hh = g * 16 + h;
            acc += v[hh] * aw[(size_t)hh * 1536 + 512 + j];
        }
        g_u2p[g * 1024 + j] = acc;
    }
}

__global__ void k_u2r() {
    int j = blockIdx.x * 256 + threadIdx.x;
    float s = 0.f;
#pragma unroll
    for (int g = 0; g < 32; g++) s += g_u2p[g * 1024 + j];
    g_u2[j] = s;
}

// ---------------- kernel 4: attention (scores -> softmax -> context) -----------
__global__ __launch_bounds__(256) void k_attn(const float* __restrict__ enc) {
    __shared__ __align__(16) float s_u2[1024];
    __shared__ float s_sc[SN];
    __shared__ float s_red[8];
    int tid = threadIdx.x, wid = tid >> 5, lid = tid & 31;
    int b = blockIdx.x;

    for (int i = tid; i < 1024; i += 256) s_u2[i] = g_u2[i];
    __syncthreads();

    // scores[s] = enc[b,s,:] . u2   (one warp per s)
    const float4* u24 = (const float4*)s_u2;
    for (int s = wid; s < SN; s += 8) {
        const float4* row = (const float4*)(enc + ((size_t)b * SN + s) * 1024);
        float acc = 0.f;
        for (int j = lid; j < 256; j += 32) {
            float4 e = row[j];
            float4 u = u24[j];
            acc += e.x * u.x + e.y * u.y + e.z * u.z + e.w * u.w;
        }
#pragma unroll
        for (int o = 16; o; o >>= 1) acc += __shfl_xor_sync(0xffffffffu, acc, o);
        if (lid == 0) s_sc[s] = acc;
    }
    __syncthreads();

    // softmax max
    float m = -1e30f;
    for (int s = tid; s < SN; s += 256) m = fmaxf(m, s_sc[s]);
#pragma unroll
    for (int o = 16; o; o >>= 1) m = fmaxf(m, __shfl_xor_sync(0xffffffffu, m, o));
    if (lid == 0) s_red[wid] = m;
    __syncthreads();
    if (tid == 0) {
        float mm = s_red[0];
#pragma unroll
        for (int i = 1; i < 8; i++) mm = fmaxf(mm, s_red[i]);
        s_red[0] = mm;
    }
    __syncthreads();
    float gm = s_red[0];
    __syncthreads();

    // exp + sum (unnormalized; fold 1/sum into context)
    float sum = 0.f;
    for (int s = tid; s < SN; s += 256) {
        float e = expf(s_sc[s] - gm);
        s_sc[s] = e;
        sum += e;
    }
#pragma unroll
    for (int o = 16; o; o >>= 1) sum += __shfl_xor_sync(0xffffffffu, sum, o);
    if (lid == 0) s_red[wid] = sum;
    __syncthreads();
    if (tid == 0) {
        float t = 0.f;
#pragma unroll
        for (int i = 0; i < 8; i++) t += s_red[i];
        s_red[0] = t;
    }
    __syncthreads();
    float inv = 1.0f / s_red[0];

    // context[d] = sum_s p[s] * enc[b,s,d]  (second pass -> L2 hits)
    float a0 = 0.f, a1 = 0.f, a2 = 0.f, a3 = 0.f;
    const float* base = enc + (size_t)b * SN * 1024;
    for (int s = 0; s < SN; s++) {
        float p = s_sc[s];
        const float* r = base + (size_t)s * 1024;
        a0 += p * r[tid];
        a1 += p * r[tid + 256];
        a2 += p * r[tid + 512];
        a3 += p * r[tid + 768];
    }
    g_to[b * KT + 512 + tid]       = a0 * inv;
    g_to[b * KT + 512 + tid + 256] = a1 * inv;
    g_to[b * KT + 512 + tid + 512] = a2 * inv;
    g_to[b * KT + 512 + tid + 768] = a3 * inv;
}

// ---------------- kernel 5: GRU cell -------------------------------------------
__global__ __launch_bounds__(256) void k_gru(
    const float* __restrict__ hid, const float* __restrict__ wih,
    const float* __restrict__ whh, const float* __restrict__ bih,
    const float* __restrict__ bhh, float* __restrict__ outh) {
    __shared__ __align__(16) float s_tg[GIN];
    __shared__ __align__(16) float s_h0[HN];
    int tid = threadIdx.x, wid = tid >> 5, lid = tid & 31;
    int b = blockIdx.x >> 1;
    int half = blockIdx.x & 1;

    for (int i = tid; i < GIN; i += 256) {
        float xv = (i < EN) ? g_to[b * KT + 1536 + i] : g_to[b * KT + 512 + (i - EN)];
        s_tg[i] = fmaxf(xv, 0.f);  // relu(concat(emb_x, context))
    }
    for (int i = tid; i < HN; i += 256) s_h0[i] = hid[b * HN + i];
    __syncthreads();

    const float4* tg4 = (const float4*)s_tg;
    const float4* h04 = (const float4*)s_h0;
    for (int kk = 0; kk < 32; kk++) {
        int k = half * 256 + kk * 8 + wid;
        float ar = 0.f, az = 0.f, an = 0.f, br = 0.f, bz = 0.f, bn = 0.f;
        const float4* wr = (const float4*)(wih + (size_t)k * GIN);
        const float4* wz = (const float4*)(wih + (size_t)(k + 512) * GIN);
        const float4* wn = (const float4*)(wih + (size_t)(k + 1024) * GIN);
        for (int j = lid; j < GIN / 4; j += 32) {
            float4 t = tg4[j];
            float4 A = wr[j]; ar += A.x * t.x + A.y * t.y + A.z * t.z + A.w * t.w;
            float4 Bv = wz[j]; az += Bv.x * t.x + Bv.y * t.y + Bv.z * t.z + Bv.w * t.w;
            float4 C = wn[j]; an += C.x * t.x + C.y * t.y + C.z * t.z + C.w * t.w;
        }
        const float4* vr = (const float4*)(whh + (size_t)k * HN);
        const float4* vz = (const float4*)(whh + (size_t)(k + 512) * HN);
        const float4* vn = (const float4*)(whh + (size_t)(k + 1024) * HN);
        for (int j = lid; j < HN / 4; j += 32) {
            float4 t = h04[j];
            float4 A = vr[j]; br += A.x * t.x + A.y * t.y + A.z * t.z + A.w * t.w;
            float4 Bv = vz[j]; bz += Bv.x * t.x + Bv.y * t.y + Bv.z * t.z + Bv.w * t.w;
            float4 C = vn[j]; bn += C.x * t.x + C.y * t.y + C.z * t.z + C.w * t.w;
        }
#pragma unroll
        for (int o = 16; o; o >>= 1) {
            ar += __shfl_xor_sync(0xffffffffu, ar, o);
            az += __shfl_xor_sync(0xffffffffu, az, o);
            an += __shfl_xor_sync(0xffffffffu, an, o);
            br += __shfl_xor_sync(0xffffffffu, br, o);
            bz += __shfl_xor_sync(0xffffffffu, bz, o);
            bn += __shfl_xor_sync(0xffffffffu, bn, o);
        }
        if (lid == 0) {
            float gr = ar + bih[k] + br + bhh[k];
            float gz = az + bih[k + 512] + bz + bhh[k + 512];
            float r = 1.f / (1.f + expf(-gr));
            float z = 1.f / (1.f + expf(-gz));
            float n = tanhf(an + bih[k + 1024] + r * (bn + bhh[k + 1024]));
            float h = (1.f - z) * n + z * s_h0[k];
            g_to[b * KT + k] = h;          // to_out[:, 0:512] = h_new
            outh[b * HN + k] = h;          // second output
        }
    }
}

// ---------------- kernel 6: split to_out into bf16 hi/lo -----------------------
__global__ void k_conv() {
    int b = blockIdx.x;
    for (int i = threadIdx.x; i < KT; i += 256) {
        float xv = g_to[b * KT + i];
        __nv_bfloat16 hx = __float2bfloat16(xv);
        g_ahi[b * KT + i] = hx;
        g_alo[b * KT + i] = __float2bfloat16(xv - __bfloat162float(hx));
    }
}

// ---------------- kernel 7: logits via mma.sync split-bf16 GEMM -----------------
// C[128, 128-tile of V] = Ahi@Whi^T + Alo@Whi^T + Ahi@Wlo^T  (fp32 accumulators)
// A staged per-64-K-chunk in SMEM (SW128-swizzled, conflict-free); W fragments
// loaded directly from GMEM as fp32 (32B-sector coalesced) and split in regs.
// 8 warps in a 2(m) x 4(n) grid; warp tile 64m x 32n; mma.sync.m16n8k16 bf16.

__device__ __forceinline__ void mma16816(float* c, const uint32_t* a, uint32_t b0, uint32_t b1) {
    asm volatile(
        "mma.sync.aligned.m16n8k16.row.col.f32.bf16.bf16.f32 "
        "{%0,%1,%2,%3}, {%4,%5,%6,%7}, {%8,%9}, {%0,%1,%2,%3};"
        : "+f"(c[0]), "+f"(c[1]), "+f"(c[2]), "+f"(c[3])
        : "r"(a[0]), "r"(a[1]), "r"(a[2]), "r"(a[3]), "r"(b0), "r"(b1));
}

__global__ __launch_bounds__(256, 2) void k_logits(const float* __restrict__ W,
                                                   const float* __restrict__ bias,
                                                   float* __restrict__ out) {
    __shared__ __align__(128) char s_ahi[16384];   // 128 rows x 128B (64 bf16)
    __shared__ __align__(128) char s_alo[16384];

    int tid = threadIdx.x, wid = tid >> 5, lid = tid & 31;
    int v0 = blockIdx.x * 128;
    int warpM = (wid & 1) * 64;       // 2 m-warps
    int warpN = (wid >> 1) * 32;      // 4 n-warps
    int lr = lid >> 2;                // 0..7 : fragment row / n index
    int lq = lid & 3;                 // 0..3 : k-pair quad

    float c[4][4][4];                 // [m-tile][n-tile][frag]
#pragma unroll
    for (int mt = 0; mt < 4; mt++)
#pragma unroll
        for (int nt = 0; nt < 4; nt++)
#pragma unroll
            for (int j = 0; j < 4; j++) c[mt][nt][j] = 0.f;

    for (int ch = 0; ch < 28; ch++) {  // K chunks of 64
        // stage A hi/lo chunk: 128 rows x 8 segs of 16B = 1024 slots, 256 thr x 4
        const char* ah = (const char*)g_ahi + ch * 128;
        const char* al = (const char*)g_alo + ch * 128;
#pragma unroll
        for (int i = 0; i < 4; i++) {
            int q = tid + i * 256;
            int row = q >> 3, seg = q & 7;
            uint32_t off = (uint32_t)(row * 128 + seg * 16);
            uint32_t sw = SWZ128(off);
            *(uint4*)(s_ahi + sw) = *(const uint4*)(ah + (size_t)row * (KT * 2) + seg * 16);
            *(uint4*)(s_alo + sw) = *(const uint4*)(al + (size_t)row * (KT * 2) + seg * 16);
        }
        __syncthreads();

#pragma unroll
        for (int s = 0; s < 4; s++) {  // k-steps of 16 within chunk
            // ---- A fragments from SMEM (conflict-free under SW128) ----
            uint32_t ahi[4][4], alo[4][4];
#pragma unroll
            for (int mt = 0; mt < 4; mt++) {
                int r0 = warpM + mt * 16 + lr;
                uint32_t o00 = (uint32_t)(r0 * 128 + s * 32 + lq * 4);
                uint32_t o10 = (uint32_t)((r0 + 8) * 128 + s * 32 + lq * 4);
                ahi[mt][0] = *(const uint32_t*)(s_ahi + SWZ128(o00));
                ahi[mt][1] = *(const uint32_t*)(s_ahi + SWZ128(o10));
                ahi[mt][2] = *(const uint32_t*)(s_ahi + SWZ128(o00 + 16));
                ahi[mt][3] = *(const uint32_t*)(s_ahi + SWZ128(o10 + 16));
                alo[mt][0] = *(const uint32_t*)(s_alo + SWZ128(o00));
                alo[mt][1] = *(const uint32_t*)(s_alo + SWZ128(o10));
                alo[mt][2] = *(const uint32_t*)(s_alo + SWZ128(o00 + 16));
                alo[mt][3] = *(const uint32_t*)(s_alo + SWZ128(o10 + 16));
            }
#pragma unroll
            for (int nt = 0; nt < 4; nt++) {
                // ---- W fragment: fp32 from GMEM, split to bf16 hi/lo ----
                int vr = v0 + warpN + nt * 8 + lr;
                float2 w0 = make_float2(0.f, 0.f), w1 = make_float2(0.f, 0.f);
                if (vr < VN) {
                    const float* wp = W + (size_t)vr * KT + ch * 64 + s * 16 + lq * 2;
                    w0 = *(const float2*)(wp);
                    w1 = *(const float2*)(wp + 8);
                }
                __nv_bfloat162 h0 = __floats2bfloat162_rn(w0.x, w0.y);  // .x -> low half
                __nv_bfloat162 h1 = __floats2bfloat162_rn(w1.x, w1.y);
                __nv_bfloat162 l0 = __floats2bfloat162_rn(
                    w0.x - __bfloat162float(__low2bfloat16(h0)),
                    w0.y - __bfloat162float(__high2bfloat16(h0)));
                __nv_bfloat162 l1 = __floats2bfloat162_rn(
                    w1.x - __bfloat162float(__low2bfloat16(h1)),
                    w1.y - __bfloat162float(__high2bfloat16(h1)));
                uint32_t bh0 = *(uint32_t*)&h0, bh1 = *(uint32_t*)&h1;
                uint32_t bl0 = *(uint32_t*)&l0, bl1 = *(uint32_t*)&l1;
#pragma unroll
                for (int mt = 0; mt < 4; mt++) mma16816(c[mt][nt], ahi[mt], bh0, bh1);
#pragma unroll
                for (int mt = 0; mt < 4; mt++) mma16816(c[mt][nt], alo[mt], bh0, bh1);
#pragma unroll
                for (int mt = 0; mt < 4; mt++) mma16816(c[mt][nt], ahi[mt], bl0, bl1);
            }
        }
        __syncthreads();
    }

    // epilogue: add bias, store
#pragma unroll
    for (int nt = 0; nt < 4; nt++) {
        int col = v0 + warpN + nt * 8 + lq * 2;
        float b0 = 0.f, b1 = 0.f;
        if (col < VN) b0 = bias[col];
        if (col + 1 < VN) b1 = bias[col + 1];
#pragma unroll
        for (int mt = 0; mt < 4; mt++) {
            int row = warpM + mt * 16 + lr;
            if (col < VN) {
                out[(size_t)row * VN + col]       = c[mt][nt][0] + b0;
                out[(size_t)(row + 8) * VN + col] = c[mt][nt][2] + b0;
            }
            if (col + 1 < VN) {
                out[(size_t)row * VN + col + 1]       = c[mt][nt][1] + b1;
                out[(size_t)(row + 8) * VN + col + 1] = c[mt][nt][3] + b1;
            }
        }
    }
}

// ---------------- launch --------------------------------------------------------
extern "C" void kernel_launch(void* const* d_in, const int* in_sizes, int n_in,
                              void* d_out, int out_size) {
    const int*   x      = (const int*)d_in[0];
    const float* hidden = (const float*)d_in[1];
    const float* enc    = (const float*)d_in[2];
    const float* emb    = (const float*)d_in[3];
    const float* attn_w = (const float*)d_in[4];
    // d_in[5] = attn_b (softmax-invariant, unused)
    const float* v      = (const float*)d_in[6];
    const float* w_ih   = (const float*)d_in[7];
    const float* w_hh   = (const float*)d_in[8];
    const float* b_ih   = (const float*)d_in[9];
    const float* b_hh   = (const float*)d_in[10];
    const float* out_w  = (const float*)d_in[11];
    const float* out_b  = (const float*)d_in[12];
    float* out = (float*)d_out;

    k_emb<<<BN, 256>>>(x, emb);
    k_u2p<<<32, 256>>>(attn_w, v);
    k_u2r<<<4, 256>>>();
    k_attn<<<BN, 256>>>(enc);
    k_gru<<<2 * BN, 256>>>(hidden, w_ih, w_hh, b_ih, b_hh, out + (size_t)BN * VN);
    k_conv<<<BN, 256>>>();

    k_logits<<<(VN + 127) / 128, 256>>>(out_w, out_b, out);
}

// round 5
// speedup vs baseline: 1.6764x; 1.6764x over previous
#include <cuda_runtime.h>
#include <cuda_bf16.h>
#include <cstdint>

#define BN 128
#define HN 512
#define EN 256
#define VN 50000
#define SN 200
#define KT 1792     // 3H + E
#define GIN 1280    // 2H + E

// ---------------- device scratch (allocation-free rule: __device__ globals) ----
__device__ float g_u2p[32 * 1024];
__device__ float g_u2[1024];
__device__ float g_to[BN * KT];               // to_out = [h_new | context | emb_x]
__device__ __align__(16) __nv_bfloat16 g_ahi[BN * KT];
__device__ __align__(16) __nv_bfloat16 g_alo[BN * KT];

#define SWZ128(o) ((o) ^ (((o) >> 3) & 0x70))

__device__ __forceinline__ uint32_t smem_cast(const void* p) {
    return (uint32_t)__cvta_generic_to_shared(p);
}

#define CP_ASYNC16(s, g) asm volatile("cp.async.cg.shared.global [%0], [%1], 16;" :: "r"(s), "l"(g))
#define CP_COMMIT()      asm volatile("cp.async.commit_group;" ::: "memory")
#define CP_WAIT_ALL()    asm volatile("cp.async.wait_all;" ::: "memory")
#define CP_WAIT1()       asm volatile("cp.async.wait_group 1;" ::: "memory")
#define CP_WAIT0()       asm volatile("cp.async.wait_group 0;" ::: "memory")

// ---------------- kernel 1: emb gather into to_out[:, 1536:1792] ---------------
__global__ void k_emb(const int* __restrict__ x, const float* __restrict__ emb) {
    int b = blockIdx.x;
    g_to[b * KT + 1536 + threadIdx.x] = emb[(size_t)x[b] * EN + threadIdx.x];
}

// ---------------- kernel 2/3: u2 = attn_w[:, H:3H].T @ v (partial + reduce) ----
__global__ void k_u2p(const float* __restrict__ aw, const float* __restrict__ v) {
    int g = blockIdx.x;  // h-range [g*16, g*16+16)
    for (int jj = 0; jj < 4; jj++) {
        int j = threadIdx.x + jj * 256;
        float acc = 0.f;
#pragma unroll
        for (int h = 0; h < 16; h++) {
            int hh = g * 16 + h;
            acc += v[hh] * aw[(size_t)hh * 1536 + 512 + j];
        }
        g_u2p[g * 1024 + j] = acc;
    }
}

__global__ void k_u2r() {
    int j = blockIdx.x * 256 + threadIdx.x;
    float s = 0.f;
#pragma unroll
    for (int g = 0; g < 32; g++) s += g_u2p[g * 1024 + j];
    g_u2[j] = s;
}

// ---------------- kernel 4: attention, single DRAM pass (online softmax) -------
// One CTA per b. 16-row enc tiles double-buffered via cp.async.
// Each thread owns 4 context dims; tile scores shared via SMEM.
#define ATTN_SMEM ((2 * 16 * 1024 + 1024) * 4)

__global__ __launch_bounds__(256) void k_attn(const float* __restrict__ enc) {
    extern __shared__ float sm[];
    float* s_enc = sm;                    // [2][16*1024]
    float* s_u2 = sm + 2 * 16 * 1024;     // [1024]
    __shared__ float s_sc[16];
    int tid = threadIdx.x, wid = tid >> 5, lid = tid & 31;
    int b = blockIdx.x;
    const float* base = enc + (size_t)b * SN * 1024;

    for (int i = tid; i < 1024; i += 256) s_u2[i] = g_u2[i];

    // prefetch tile 0 (16 rows x 4KB)
    {
        uint32_t sa = smem_cast(s_enc);
        for (int u = tid; u < 16 * 256; u += 256)
            CP_ASYNC16(sa + u * 16, (const char*)base + (size_t)u * 16);
        CP_COMMIT();
    }

    float m = -1e30f, sum = 0.f;
    float c0 = 0.f, c1 = 0.f, c2 = 0.f, c3 = 0.f;
    const int NT = 13;  // 12 x 16 + 8
    for (int t = 0; t < NT; t++) {
        int nr = (t == NT - 1) ? (SN - 16 * (NT - 1)) : 16;
        float* buf = s_enc + (t & 1) * 16 * 1024;
        if (t + 1 < NT) {
            int nr2 = (t + 1 == NT - 1) ? (SN - 16 * (NT - 1)) : 16;
            uint32_t sa = smem_cast(s_enc + ((t + 1) & 1) * 16 * 1024);
            const char* g = (const char*)(base + (size_t)(t + 1) * 16 * 1024);
            for (int u = tid; u < nr2 * 256; u += 256)
                CP_ASYNC16(sa + u * 16, g + (size_t)u * 16);
            CP_COMMIT();
            CP_WAIT1();
        } else {
            CP_WAIT0();
        }
        __syncthreads();

        // scores for rows wid, wid+8 within tile
        const float4* u24 = (const float4*)s_u2;
        for (int j = wid; j < nr; j += 8) {
            const float4* row = (const float4*)(buf + j * 1024);
            float acc = 0.f;
#pragma unroll 4
            for (int q = lid; q < 256; q += 32) {
                float4 e = row[q], u = u24[q];
                acc += e.x * u.x + e.y * u.y + e.z * u.z + e.w * u.w;
            }
#pragma unroll
            for (int o = 16; o; o >>= 1) acc += __shfl_xor_sync(0xffffffffu, acc, o);
            if (lid == 0) s_sc[j] = acc;
        }
        __syncthreads();

        // online softmax update (each thread full copy of m/sum; 4 ctx dims)
        float nm = m;
        for (int j = 0; j < nr; j++) nm = fmaxf(nm, s_sc[j]);
        float scl = expf(m - nm);
        c0 *= scl; c1 *= scl; c2 *= scl; c3 *= scl; sum *= scl;
        for (int j = 0; j < nr; j++) {
            float p = expf(s_sc[j] - nm);
            sum += p;
            const float* r = buf + j * 1024;
            c0 += p * r[tid];
            c1 += p * r[tid + 256];
            c2 += p * r[tid + 512];
            c3 += p * r[tid + 768];
        }
        m = nm;
        __syncthreads();  // protect buf before next iteration's prefetch overwrites it
    }

    float inv = 1.0f / sum;
    g_to[b * KT + 512 + tid]       = c0 * inv;
    g_to[b * KT + 512 + tid + 256] = c1 * inv;
    g_to[b * KT + 512 + tid + 512] = c2 * inv;
    g_to[b * KT + 512 + tid + 768] = c3 * inv;
}

// ---------------- kernel 5: GRU cell, 8 b per CTA (weight reuse x8) ------------
// grid = 16 b-groups x 8 k-quads = 128 CTAs. Warp w handles 8 k-values, all 8 b.
#define GRU_SMEM ((8 * GIN + 8 * HN) * 4)

__global__ __launch_bounds__(256) void k_gru(
    const float* __restrict__ hid, const float* __restrict__ wih,
    const float* __restrict__ whh, const float* __restrict__ bih,
    const float* __restrict__ bhh, float* __restrict__ outh) {
    extern __shared__ float sm[];
    float* s_tg = sm;               // [8][1280] relu(concat(emb, ctx))
    float* s_h0 = sm + 8 * GIN;     // [8][512]
    int tid = threadIdx.x, w = tid >> 5, lid = tid & 31;
    int bg = blockIdx.x >> 3;       // 0..15
    int kq = blockIdx.x & 7;        // 0..7
    int b0 = bg * 8;

    for (int i = tid; i < 8 * GIN; i += 256) {
        int bb = i / GIN, ii = i - bb * GIN;
        int b = b0 + bb;
        float v = (ii < EN) ? g_to[b * KT + 1536 + ii] : g_to[b * KT + 512 + (ii - EN)];
        s_tg[i] = fmaxf(v, 0.f);
    }
    for (int i = tid; i < 8 * HN; i += 256) {
        int bb = i >> 9, ii = i & 511;
        s_h0[i] = hid[(b0 + bb) * HN + ii];
    }
    __syncthreads();

    for (int kk = 0; kk < 8; kk++) {
        int k = kq * 64 + w * 8 + kk;
        float ar[8], az[8], an[8], ahn[8];
#pragma unroll
        for (int bb = 0; bb < 8; bb++) { ar[bb] = az[bb] = an[bb] = ahn[bb] = 0.f; }

        const float4* wr = (const float4*)(wih + (size_t)k * GIN);
        const float4* wz = (const float4*)(wih + (size_t)(k + 512) * GIN);
        const float4* wn = (const float4*)(wih + (size_t)(k + 1024) * GIN);
        for (int j = lid; j < GIN / 4; j += 32) {
            float4 A = wr[j], B = wz[j], C = wn[j];
#pragma unroll
            for (int bb = 0; bb < 8; bb++) {
                float4 t = ((const float4*)(s_tg + bb * GIN))[j];
                ar[bb] += A.x * t.x + A.y * t.y + A.z * t.z + A.w * t.w;
                az[bb] += B.x * t.x + B.y * t.y + B.z * t.z + B.w * t.w;
                an[bb] += C.x * t.x + C.y * t.y + C.z * t.z + C.w * t.w;
            }
        }
        const float4* vr = (const float4*)(whh + (size_t)k * HN);
        const float4* vz = (const float4*)(whh + (size_t)(k + 512) * HN);
        const float4* vn = (const float4*)(whh + (size_t)(k + 1024) * HN);
        for (int j = lid; j < HN / 4; j += 32) {
            float4 A = vr[j], B = vz[j], C = vn[j];
#pragma unroll
            for (int bb = 0; bb < 8; bb++) {
                float4 t = ((const float4*)(s_h0 + bb * HN))[j];
                ar[bb] += A.x * t.x + A.y * t.y + A.z * t.z + A.w * t.w;
                az[bb] += B.x * t.x + B.y * t.y + B.z * t.z + B.w * t.w;
                ahn[bb] += C.x * t.x + C.y * t.y + C.z * t.z + C.w * t.w;
            }
        }
#pragma unroll
        for (int o = 16; o; o >>= 1) {
#pragma unroll
            for (int bb = 0; bb < 8; bb++) {
                ar[bb] += __shfl_xor_sync(0xffffffffu, ar[bb], o);
                az[bb] += __shfl_xor_sync(0xffffffffu, az[bb], o);
                an[bb] += __shfl_xor_sync(0xffffffffu, an[bb], o);
                ahn[bb] += __shfl_xor_sync(0xffffffffu, ahn[bb], o);
            }
        }
        if (lid == 0) {
            float br_ = bih[k] + bhh[k];
            float bz_ = bih[k + 512] + bhh[k + 512];
            float bin = bih[k + 1024], bhn = bhh[k + 1024];
#pragma unroll
            for (int bb = 0; bb < 8; bb++) {
                float r = 1.f / (1.f + expf(-(ar[bb] + br_)));
                float z = 1.f / (1.f + expf(-(az[bb] + bz_)));
                float n = tanhf(an[bb] + bin + r * (ahn[bb] + bhn));
                float h = (1.f - z) * n + z * s_h0[bb * HN + k];
                g_to[(b0 + bb) * KT + k] = h;
                outh[(b0 + bb) * HN + k] = h;
            }
        }
    }
}

// ---------------- kernel 6: split to_out into bf16 hi/lo -----------------------
__global__ void k_conv() {
    int b = blockIdx.x;
    for (int i = threadIdx.x; i < KT; i += 256) {
        float xv = g_to[b * KT + i];
        __nv_bfloat16 hx = __float2bfloat16(xv);
        g_ahi[b * KT + i] = hx;
        g_alo[b * KT + i] = __float2bfloat16(xv - __bfloat162float(hx));
    }
}

// ---------------- kernel 7: logits via mma.sync split-bf16 GEMM -----------------
// CTA tile 128m x 64n (lean registers: no spill at 2 CTA/SM). 8 warps 2(m)x4(n),
// warp tile 64m x 16n. A staged via cp.async + ldmatrix.x4; W fp32 direct from
// GMEM, software-pipelined one k-step ahead, split to bf16 hi/lo in registers.

__device__ __forceinline__ void mma16816(float* c, const uint32_t* a, uint32_t b0, uint32_t b1) {
    asm volatile(
        "mma.sync.aligned.m16n8k16.row.col.f32.bf16.bf16.f32 "
        "{%0,%1,%2,%3}, {%4,%5,%6,%7}, {%8,%9}, {%0,%1,%2,%3};"
        : "+f"(c[0]), "+f"(c[1]), "+f"(c[2]), "+f"(c[3])
        : "r"(a[0]), "r"(a[1]), "r"(a[2]), "r"(a[3]), "r"(b0), "r"(b1));
}

__global__ __launch_bounds__(256, 2) void k_logits(const float* __restrict__ W,
                                                   const float* __restrict__ bias,
                                                   float* __restrict__ out) {
    __shared__ __align__(128) char s_ahi[16384];   // 128 rows x 128B (64 bf16)
    __shared__ __align__(128) char s_alo[16384];

    int tid = threadIdx.x, wid = tid >> 5, lid = tid & 31;
    int v0 = blockIdx.x * 64;
    int warpM = (wid & 1) * 64;
    int warpN = (wid >> 1) * 16;
    int lr = lid >> 2, lq = lid & 3;
    int lrow = lid & 15;              // ldmatrix row-within-16
    int lcolh = (lid >> 4) * 16;      // ldmatrix 16B column half

    uint32_t sa_hi = smem_cast(s_ahi), sa_lo = smem_cast(s_alo);

    const float* wptr[2];
    bool wok[2];
#pragma unroll
    for (int nt = 0; nt < 2; nt++) {
        int vr = v0 + warpN + nt * 8 + lr;
        wok[nt] = (vr < VN);
        wptr[nt] = W + (size_t)(wok[nt] ? vr : 0) * KT;
    }

    float c[4][2][4];
#pragma unroll
    for (int mt = 0; mt < 4; mt++)
#pragma unroll
        for (int nt = 0; nt < 2; nt++)
#pragma unroll
            for (int j = 0; j < 4; j++) c[mt][nt][j] = 0.f;

    for (int ch = 0; ch < 28; ch++) {
        // stage A hi/lo chunk: 128 rows x 8 segs of 16B via cp.async
        const char* ah = (const char*)g_ahi + ch * 128;
        const char* al = (const char*)g_alo + ch * 128;
#pragma unroll
        for (int i = 0; i < 4; i++) {
            int q = tid + i * 256;
            int row = q >> 3, seg = q & 7;
            uint32_t sw = SWZ128((uint32_t)(row * 128 + seg * 16));
            CP_ASYNC16(sa_hi + sw, ah + (size_t)row * (KT * 2) + seg * 16);
            CP_ASYNC16(sa_lo + sw, al + (size_t)row * (KT * 2) + seg * 16);
        }
        CP_COMMIT();
        CP_WAIT_ALL();
        __syncthreads();

        // preload W fragments for s = 0
        float2 cw0[2], cw1[2];
#pragma unroll
        for (int nt = 0; nt < 2; nt++) {
            cw0[nt] = make_float2(0.f, 0.f);
            cw1[nt] = make_float2(0.f, 0.f);
            if (wok[nt]) {
                const float* wp = wptr[nt] + ch * 64 + lq * 2;
                cw0[nt] = *(const float2*)wp;
                cw1[nt] = *(const float2*)(wp + 8);
            }
        }

#pragma unroll
        for (int s = 0; s < 4; s++) {
            // A fragments via ldmatrix.x4 (order matches mma.sync A layout)
            uint32_t ahi[4][4], alo[4][4];
#pragma unroll
            for (int mt = 0; mt < 4; mt++) {
                int row = warpM + mt * 16 + lrow;
                uint32_t off = SWZ128((uint32_t)(row * 128 + s * 32 + lcolh));
                asm volatile("ldmatrix.sync.aligned.m8n8.x4.shared.b16 {%0,%1,%2,%3}, [%4];"
                             : "=r"(ahi[mt][0]), "=r"(ahi[mt][1]), "=r"(ahi[mt][2]), "=r"(ahi[mt][3])
                             : "r"(sa_hi + off));
                asm volatile("ldmatrix.sync.aligned.m8n8.x4.shared.b16 {%0,%1,%2,%3}, [%4];"
                             : "=r"(alo[mt][0]), "=r"(alo[mt][1]), "=r"(alo[mt][2]), "=r"(alo[mt][3])
                             : "r"(sa_lo + off));
            }
            // prefetch W for s+1
            float2 nw0[2], nw1[2];
            if (s < 3) {
#pragma unroll
                for (int nt = 0; nt < 2; nt++) {
                    nw0[nt] = make_float2(0.f, 0.f);
                    nw1[nt] = make_float2(0.f, 0.f);
                    if (wok[nt]) {
                        const float* wp = wptr[nt] + ch * 64 + (s + 1) * 16 + lq * 2;
                        nw0[nt] = *(const float2*)wp;
                        nw1[nt] = *(const float2*)(wp + 8);
                    }
                }
            }
#pragma unroll
            for (int nt = 0; nt < 2; nt++) {
                __nv_bfloat162 h0 = __floats2bfloat162_rn(cw0[nt].x, cw0[nt].y);  // .x -> low half
                __nv_bfloat162 h1 = __floats2bfloat162_rn(cw1[nt].x, cw1[nt].y);
                __nv_bfloat162 l0 = __floats2bfloat162_rn(
                    cw0[nt].x - __bfloat162float(__low2bfloat16(h0)),
                    cw0[nt].y - __bfloat162float(__high2bfloat16(h0)));
                __nv_bfloat162 l1 = __floats2bfloat162_rn(
                    cw1[nt].x - __bfloat162float(__low2bfloat16(h1)),
                    cw1[nt].y - __bfloat162float(__high2bfloat16(h1)));
                uint32_t bh0 = *(uint32_t*)&h0, bh1 = *(uint32_t*)&h1;
                uint32_t bl0 = *(uint32_t*)&l0, bl1 = *(uint32_t*)&l1;
#pragma unroll
                for (int mt = 0; mt < 4; mt++) mma16816(c[mt][nt], ahi[mt], bh0, bh1);
#pragma unroll
                for (int mt = 0; mt < 4; mt++) mma16816(c[mt][nt], alo[mt], bh0, bh1);
#pragma unroll
                for (int mt = 0; mt < 4; mt++) mma16816(c[mt][nt], ahi[mt], bl0, bl1);
            }
            if (s < 3) {
#pragma unroll
                for (int nt = 0; nt < 2; nt++) { cw0[nt] = nw0[nt]; cw1[nt] = nw1[nt]; }
            }
        }
        __syncthreads();
    }

    // epilogue: add bias, store
#pragma unroll
    for (int nt = 0; nt < 2; nt++) {
        int col = v0 + warpN + nt * 8 + lq * 2;
        float b0 = 0.f, b1 = 0.f;
        if (col < VN) b0 = bias[col];
        if (col + 1 < VN) b1 = bias[col + 1];
#pragma unroll
        for (int mt = 0; mt < 4; mt++) {
            int row = warpM + mt * 16 + lr;
            if (col < VN) {
                out[(size_t)row * VN + col]       = c[mt][nt][0] + b0;
                out[(size_t)(row + 8) * VN + col] = c[mt][nt][2] + b0;
            }
            if (col + 1 < VN) {
                out[(size_t)row * VN + col + 1]       = c[mt][nt][1] + b1;
                out[(size_t)(row + 8) * VN + col + 1] = c[mt][nt][3] + b1;
            }
        }
    }
}

// ---------------- launch --------------------------------------------------------
extern "C" void kernel_launch(void* const* d_in, const int* in_sizes, int n_in,
                              void* d_out, int out_size) {
    const int*   x      = (const int*)d_in[0];
    const float* hidden = (const float*)d_in[1];
    const float* enc    = (const float*)d_in[2];
    const float* emb    = (const float*)d_in[3];
    const float* attn_w = (const float*)d_in[4];
    // d_in[5] = attn_b (softmax-invariant, unused)
    const float* v      = (const float*)d_in[6];
    const float* w_ih   = (const float*)d_in[7];
    const float* w_hh   = (const float*)d_in[8];
    const float* b_ih   = (const float*)d_in[9];
    const float* b_hh   = (const float*)d_in[10];
    const float* out_w  = (const float*)d_in[11];
    const float* out_b  = (const float*)d_in[12];
    float* out = (float*)d_out;

    cudaFuncSetAttribute(k_attn, cudaFuncAttributeMaxDynamicSharedMemorySize, ATTN_SMEM);
    cudaFuncSetAttribute(k_gru, cudaFuncAttributeMaxDynamicSharedMemorySize, GRU_SMEM);

    k_emb<<<BN, 256>>>(x, emb);
    k_u2p<<<32, 256>>>(attn_w, v);
    k_u2r<<<4, 256>>>();
    k_attn<<<BN, 256, ATTN_SMEM>>>(enc);
    k_gru<<<BN, 256, GRU_SMEM>>>(hidden, w_ih, w_hh, b_ih, b_hh, out + (size_t)BN * VN);
    k_conv<<<BN, 256>>>();

    k_logits<<<(VN + 63) / 64, 256>>>(out_w, out_b, out);
}

// round 6
// speedup vs baseline: 1.8874x; 1.1259x over previous
#include <cuda_runtime.h>
#include <cuda_bf16.h>
#include <cuda_fp16.h>
#include <cstdint>

#define BN 128
#define HN 512
#define EN 256
#define VN 50000
#define SN 200
#define KT 1792     // 3H + E
#define GIN 1280    // 2H + E

// ---------------- device scratch (allocation-free rule: __device__ globals) ----
__device__ float g_u2p[32 * 1024];
__device__ float g_u2[1024];
__device__ float g_to[BN * KT];               // to_out = [h_new | context | emb_x]
__device__ __align__(16) __half g_ahi[BN * KT];
__device__ __align__(16) __half g_alo[BN * KT];

#define SWZ128(o) ((o) ^ (((o) >> 3) & 0x70))

__device__ __forceinline__ uint32_t smem_cast(const void* p) {
    return (uint32_t)__cvta_generic_to_shared(p);
}

#define CP_ASYNC16(s, g) asm volatile("cp.async.cg.shared.global [%0], [%1], 16;" :: "r"(s), "l"(g))
#define CP_COMMIT()      asm volatile("cp.async.commit_group;" ::: "memory")
#define CP_WAIT_ALL()    asm volatile("cp.async.wait_all;" ::: "memory")
#define CP_WAIT1()       asm volatile("cp.async.wait_group 1;" ::: "memory")
#define CP_WAIT0()       asm volatile("cp.async.wait_group 0;" ::: "memory")

// ---------------- kernel 1: emb gather into to_out[:, 1536:1792] ---------------
__global__ void k_emb(const int* __restrict__ x, const float* __restrict__ emb) {
    int b = blockIdx.x;
    g_to[b * KT + 1536 + threadIdx.x] = emb[(size_t)x[b] * EN + threadIdx.x];
}

// ---------------- kernel 2/3: u2 = attn_w[:, H:3H].T @ v (partial + reduce) ----
__global__ void k_u2p(const float* __restrict__ aw, const float* __restrict__ v) {
    int g = blockIdx.x;  // h-range [g*16, g*16+16)
    for (int jj = 0; jj < 4; jj++) {
        int j = threadIdx.x + jj * 256;
        float acc = 0.f;
#pragma unroll
        for (int h = 0; h < 16; h++) {
            int hh = g * 16 + h;
            acc += v[hh] * aw[(size_t)hh * 1536 + 512 + j];
        }
        g_u2p[g * 1024 + j] = acc;
    }
}

__global__ void k_u2r() {
    int j = blockIdx.x * 256 + threadIdx.x;
    float s = 0.f;
#pragma unroll
    for (int g = 0; g < 32; g++) s += g_u2p[g * 1024 + j];
    g_u2[j] = s;
}

// ---------------- kernel 4: attention, single DRAM pass (online softmax) -------
#define ATTN_SMEM ((2 * 16 * 1024 + 1024) * 4)

__global__ __launch_bounds__(256) void k_attn(const float* __restrict__ enc) {
    extern __shared__ float sm[];
    float* s_enc = sm;                    // [2][16*1024]
    float* s_u2 = sm + 2 * 16 * 1024;     // [1024]
    __shared__ float s_sc[16];
    int tid = threadIdx.x, wid = tid >> 5, lid = tid & 31;
    int b = blockIdx.x;
    const float* base = enc + (size_t)b * SN * 1024;

    for (int i = tid; i < 1024; i += 256) s_u2[i] = g_u2[i];

    // prefetch tile 0 (16 rows x 4KB)
    {
        uint32_t sa = smem_cast(s_enc);
        for (int u = tid; u < 16 * 256; u += 256)
            CP_ASYNC16(sa + u * 16, (const char*)base + (size_t)u * 16);
        CP_COMMIT();
    }

    float m = -1e30f, sum = 0.f;
    float c0 = 0.f, c1 = 0.f, c2 = 0.f, c3 = 0.f;
    const int NT = 13;  // 12 x 16 + 8
    for (int t = 0; t < NT; t++) {
        int nr = (t == NT - 1) ? (SN - 16 * (NT - 1)) : 16;
        float* buf = s_enc + (t & 1) * 16 * 1024;
        if (t + 1 < NT) {
            int nr2 = (t + 1 == NT - 1) ? (SN - 16 * (NT - 1)) : 16;
            uint32_t sa = smem_cast(s_enc + ((t + 1) & 1) * 16 * 1024);
            const char* g = (const char*)(base + (size_t)(t + 1) * 16 * 1024);
            for (int u = tid; u < nr2 * 256; u += 256)
                CP_ASYNC16(sa + u * 16, g + (size_t)u * 16);
            CP_COMMIT();
            CP_WAIT1();
        } else {
            CP_WAIT0();
        }
        __syncthreads();

        const float4* u24 = (const float4*)s_u2;
        for (int j = wid; j < nr; j += 8) {
            const float4* row = (const float4*)(buf + j * 1024);
            float acc = 0.f;
#pragma unroll 4
            for (int q = lid; q < 256; q += 32) {
                float4 e = row[q], u = u24[q];
                acc += e.x * u.x + e.y * u.y + e.z * u.z + e.w * u.w;
            }
#pragma unroll
            for (int o = 16; o; o >>= 1) acc += __shfl_xor_sync(0xffffffffu, acc, o);
            if (lid == 0) s_sc[j] = acc;
        }
        __syncthreads();

        float nm = m;
        for (int j = 0; j < nr; j++) nm = fmaxf(nm, s_sc[j]);
        float scl = expf(m - nm);
        c0 *= scl; c1 *= scl; c2 *= scl; c3 *= scl; sum *= scl;
        for (int j = 0; j < nr; j++) {
            float p = expf(s_sc[j] - nm);
            sum += p;
            const float* r = buf + j * 1024;
            c0 += p * r[tid];
            c1 += p * r[tid + 256];
            c2 += p * r[tid + 512];
            c3 += p * r[tid + 768];
        }
        m = nm;
        __syncthreads();
    }

    float inv = 1.0f / sum;
    g_to[b * KT + 512 + tid]       = c0 * inv;
    g_to[b * KT + 512 + tid + 256] = c1 * inv;
    g_to[b * KT + 512 + tid + 512] = c2 * inv;
    g_to[b * KT + 512 + tid + 768] = c3 * inv;
}

// ---------------- kernel 5: GRU cell, 8 b per CTA (weight reuse x8) ------------
#define GRU_SMEM ((8 * GIN + 8 * HN) * 4)

__global__ __launch_bounds__(256) void k_gru(
    const float* __restrict__ hid, const float* __restrict__ wih,
    const float* __restrict__ whh, const float* __restrict__ bih,
    const float* __restrict__ bhh, float* __restrict__ outh) {
    extern __shared__ float sm[];
    float* s_tg = sm;               // [8][1280]
    float* s_h0 = sm + 8 * GIN;     // [8][512]
    int tid = threadIdx.x, w = tid >> 5, lid = tid & 31;
    int bg = blockIdx.x >> 3;
    int kq = blockIdx.x & 7;
    int b0 = bg * 8;

    for (int i = tid; i < 8 * GIN; i += 256) {
        int bb = i / GIN, ii = i - bb * GIN;
        int b = b0 + bb;
        float v = (ii < EN) ? g_to[b * KT + 1536 + ii] : g_to[b * KT + 512 + (ii - EN)];
        s_tg[i] = fmaxf(v, 0.f);
    }
    for (int i = tid; i < 8 * HN; i += 256) {
        int bb = i >> 9, ii = i & 511;
        s_h0[i] = hid[(b0 + bb) * HN + ii];
    }
    __syncthreads();

    for (int kk = 0; kk < 8; kk++) {
        int k = kq * 64 + w * 8 + kk;
        float ar[8], az[8], an[8], ahn[8];
#pragma unroll
        for (int bb = 0; bb < 8; bb++) { ar[bb] = az[bb] = an[bb] = ahn[bb] = 0.f; }

        const float4* wr = (const float4*)(wih + (size_t)k * GIN);
        const float4* wz = (const float4*)(wih + (size_t)(k + 512) * GIN);
        const float4* wn = (const float4*)(wih + (size_t)(k + 1024) * GIN);
        for (int j = lid; j < GIN / 4; j += 32) {
            float4 A = wr[j], B = wz[j], C = wn[j];
#pragma unroll
            for (int bb = 0; bb < 8; bb++) {
                float4 t = ((const float4*)(s_tg + bb * GIN))[j];
                ar[bb] += A.x * t.x + A.y * t.y + A.z * t.z + A.w * t.w;
                az[bb] += B.x * t.x + B.y * t.y + B.z * t.z + B.w * t.w;
                an[bb] += C.x * t.x + C.y * t.y + C.z * t.z + C.w * t.w;
            }
        }
        const float4* vr = (const float4*)(whh + (size_t)k * HN);
        const float4* vz = (const float4*)(whh + (size_t)(k + 512) * HN);
        const float4* vn = (const float4*)(whh + (size_t)(k + 1024) * HN);
        for (int j = lid; j < HN / 4; j += 32) {
            float4 A = vr[j], B = vz[j], C = vn[j];
#pragma unroll
            for (int bb = 0; bb < 8; bb++) {
                float4 t = ((const float4*)(s_h0 + bb * HN))[j];
                ar[bb] += A.x * t.x + A.y * t.y + A.z * t.z + A.w * t.w;
                az[bb] += B.x * t.x + B.y * t.y + B.z * t.z + B.w * t.w;
                ahn[bb] += C.x * t.x + C.y * t.y + C.z * t.z + C.w * t.w;
            }
        }
#pragma unroll
        for (int o = 16; o; o >>= 1) {
#pragma unroll
            for (int bb = 0; bb < 8; bb++) {
                ar[bb] += __shfl_xor_sync(0xffffffffu, ar[bb], o);
                az[bb] += __shfl_xor_sync(0xffffffffu, az[bb], o);
                an[bb] += __shfl_xor_sync(0xffffffffu, an[bb], o);
                ahn[bb] += __shfl_xor_sync(0xffffffffu, ahn[bb], o);
            }
        }
        if (lid == 0) {
            float br_ = bih[k] + bhh[k];
            float bz_ = bih[k + 512] + bhh[k + 512];
            float bin = bih[k + 1024], bhn = bhh[k + 1024];
#pragma unroll
            for (int bb = 0; bb < 8; bb++) {
                float r = 1.f / (1.f + expf(-(ar[bb] + br_)));
                float z = 1.f / (1.f + expf(-(az[bb] + bz_)));
                float n = tanhf(an[bb] + bin + r * (ahn[bb] + bhn));
                float h = (1.f - z) * n + z * s_h0[bb * HN + k];
                g_to[(b0 + bb) * KT + k] = h;
                outh[(b0 + bb) * HN + k] = h;
            }
        }
    }
}

// ---------------- kernel 6: split to_out into fp16 hi/lo -----------------------
__global__ void k_conv() {
    int b = blockIdx.x;
    for (int i = threadIdx.x; i < KT; i += 256) {
        float xv = g_to[b * KT + i];
        __half hx = __float2half_rn(xv);
        g_ahi[b * KT + i] = hx;
        g_alo[b * KT + i] = __float2half_rn(xv - __half2float(hx));
    }
}

// ---------------- kernel 7: logits via mma.sync split-fp16 GEMM (2 passes) -----
// C[128, 64-tile of V] = Ahi@Whi^T + Alo@Whi^T   (fp32 accumulators)
// Dropped Ahi@Wlo term ~ 2^-11 relative -> rel_err ~2e-4 < 1e-3 threshold.
// A staged via cp.async + ldmatrix.x4; W fp32 direct from GMEM -> fp16 in regs.

__device__ __forceinline__ void mma16816(float* c, const uint32_t* a, uint32_t b0, uint32_t b1) {
    asm volatile(
        "mma.sync.aligned.m16n8k16.row.col.f32.f16.f16.f32 "
        "{%0,%1,%2,%3}, {%4,%5,%6,%7}, {%8,%9}, {%0,%1,%2,%3};"
        : "+f"(c[0]), "+f"(c[1]), "+f"(c[2]), "+f"(c[3])
        : "r"(a[0]), "r"(a[1]), "r"(a[2]), "r"(a[3]), "r"(b0), "r"(b1));
}

__global__ __launch_bounds__(256, 2) void k_logits(const float* __restrict__ W,
                                                   const float* __restrict__ bias,
                                                   float* __restrict__ out) {
    __shared__ __align__(128) char s_ahi[16384];   // 128 rows x 128B (64 fp16)
    __shared__ __align__(128) char s_alo[16384];

    int tid = threadIdx.x, wid = tid >> 5, lid = tid & 31;
    int v0 = blockIdx.x * 64;
    int warpM = (wid & 1) * 64;
    int warpN = (wid >> 1) * 16;
    int lr = lid >> 2, lq = lid & 3;
    int lrow = lid & 15;
    int lcolh = (lid >> 4) * 16;

    uint32_t sa_hi = smem_cast(s_ahi), sa_lo = smem_cast(s_alo);

    const float* wptr[2];
    bool wok[2];
#pragma unroll
    for (int nt = 0; nt < 2; nt++) {
        int vr = v0 + warpN + nt * 8 + lr;
        wok[nt] = (vr < VN);
        wptr[nt] = W + (size_t)(wok[nt] ? vr : 0) * KT;
    }

    float c[4][2][4];
#pragma unroll
    for (int mt = 0; mt < 4; mt++)
#pragma unroll
        for (int nt = 0; nt < 2; nt++)
#pragma unroll
            for (int j = 0; j < 4; j++) c[mt][nt][j] = 0.f;

    for (int ch = 0; ch < 28; ch++) {
        const char* ah = (const char*)g_ahi + ch * 128;
        const char* al = (const char*)g_alo + ch * 128;
#pragma unroll
        for (int i = 0; i < 4; i++) {
            int q = tid + i * 256;
            int row = q >> 3, seg = q & 7;
            uint32_t sw = SWZ128((uint32_t)(row * 128 + seg * 16));
            CP_ASYNC16(sa_hi + sw, ah + (size_t)row * (KT * 2) + seg * 16);
            CP_ASYNC16(sa_lo + sw, al + (size_t)row * (KT * 2) + seg * 16);
        }
        CP_COMMIT();
        CP_WAIT_ALL();
        __syncthreads();

        // preload W fragments for s = 0
        float2 cw0[2], cw1[2];
#pragma unroll
        for (int nt = 0; nt < 2; nt++) {
            cw0[nt] = make_float2(0.f, 0.f);
            cw1[nt] = make_float2(0.f, 0.f);
            if (wok[nt]) {
                const float* wp = wptr[nt] + ch * 64 + lq * 2;
                cw0[nt] = *(const float2*)wp;
                cw1[nt] = *(const float2*)(wp + 8);
            }
        }

#pragma unroll
        for (int s = 0; s < 4; s++) {
            uint32_t ahi[4][4], alo[4][4];
#pragma unroll
            for (int mt = 0; mt < 4; mt++) {
                int row = warpM + mt * 16 + lrow;
                uint32_t off = SWZ128((uint32_t)(row * 128 + s * 32 + lcolh));
                asm volatile("ldmatrix.sync.aligned.m8n8.x4.shared.b16 {%0,%1,%2,%3}, [%4];"
                             : "=r"(ahi[mt][0]), "=r"(ahi[mt][1]), "=r"(ahi[mt][2]), "=r"(ahi[mt][3])
                             : "r"(sa_hi + off));
                asm volatile("ldmatrix.sync.aligned.m8n8.x4.shared.b16 {%0,%1,%2,%3}, [%4];"
                             : "=r"(alo[mt][0]), "=r"(alo[mt][1]), "=r"(alo[mt][2]), "=r"(alo[mt][3])
                             : "r"(sa_lo + off));
            }
            // prefetch W for s+1
            float2 nw0[2], nw1[2];
            if (s < 3) {
#pragma unroll
                for (int nt = 0; nt < 2; nt++) {
                    nw0[nt] = make_float2(0.f, 0.f);
                    nw1[nt] = make_float2(0.f, 0.f);
                    if (wok[nt]) {
                        const float* wp = wptr[nt] + ch * 64 + (s + 1) * 16 + lq * 2;
                        nw0[nt] = *(const float2*)wp;
                        nw1[nt] = *(const float2*)(wp + 8);
                    }
                }
            }
#pragma unroll
            for (int nt = 0; nt < 2; nt++) {
                __half2 h0 = __floats2half2_rn(cw0[nt].x, cw0[nt].y);  // .x -> low half
                __half2 h1 = __floats2half2_rn(cw1[nt].x, cw1[nt].y);
                uint32_t bh0 = *(uint32_t*)&h0, bh1 = *(uint32_t*)&h1;
#pragma unroll
                for (int mt = 0; mt < 4; mt++) mma16816(c[mt][nt], ahi[mt], bh0, bh1);
#pragma unroll
                for (int mt = 0; mt < 4; mt++) mma16816(c[mt][nt], alo[mt], bh0, bh1);
            }
            if (s < 3) {
#pragma unroll
                for (int nt = 0; nt < 2; nt++) { cw0[nt] = nw0[nt]; cw1[nt] = nw1[nt]; }
            }
        }
        __syncthreads();
    }

    // epilogue: add bias, store
#pragma unroll
    for (int nt = 0; nt < 2; nt++) {
        int col = v0 + warpN + nt * 8 + lq * 2;
        float b0 = 0.f, b1 = 0.f;
        if (col < VN) b0 = bias[col];
        if (col + 1 < VN) b1 = bias[col + 1];
#pragma unroll
        for (int mt = 0; mt < 4; mt++) {
            int row = warpM + mt * 16 + lr;
            if (col < VN) {
                out[(size_t)row * VN + col]       = c[mt][nt][0] + b0;
                out[(size_t)(row + 8) * VN + col] = c[mt][nt][2] + b0;
            }
            if (col + 1 < VN) {
                out[(size_t)row * VN + col + 1]       = c[mt][nt][1] + b1;
                out[(size_t)(row + 8) * VN + col + 1] = c[mt][nt][3] + b1;
            }
        }
    }
}

// ---------------- launch --------------------------------------------------------
extern "C" void kernel_launch(void* const* d_in, const int* in_sizes, int n_in,
                              void* d_out, int out_size) {
    const int*   x      = (const int*)d_in[0];
    const float* hidden = (const float*)d_in[1];
    const float* enc    = (const float*)d_in[2];
    const float* emb    = (const float*)d_in[3];
    const float* attn_w = (const float*)d_in[4];
    // d_in[5] = attn_b (softmax-invariant, unused)
    const float* v      = (const float*)d_in[6];
    const float* w_ih   = (const float*)d_in[7];
    const float* w_hh   = (const float*)d_in[8];
    const float* b_ih   = (const float*)d_in[9];
    const float* b_hh   = (const float*)d_in[10];
    const float* out_w  = (const float*)d_in[11];
    const float* out_b  = (const float*)d_in[12];
    float* out = (float*)d_out;

    cudaFuncSetAttribute(k_attn, cudaFuncAttributeMaxDynamicSharedMemorySize, ATTN_SMEM);
    cudaFuncSetAttribute(k_gru, cudaFuncAttributeMaxDynamicSharedMemorySize, GRU_SMEM);

    k_emb<<<BN, 256>>>(x, emb);
    k_u2p<<<32, 256>>>(attn_w, v);
    k_u2r<<<4, 256>>>();
    k_attn<<<BN, 256, ATTN_SMEM>>>(enc);
    k_gru<<<BN, 256, GRU_SMEM>>>(hidden, w_ih, w_hh, b_ih, b_hh, out + (size_t)BN * VN);
    k_conv<<<BN, 256>>>();

    k_logits<<<(VN + 63) / 64, 256>>>(out_w, out_b, out);
}

// round 7
// speedup vs baseline: 2.0164x; 1.0683x over previous
#include <cuda_runtime.h>
#include <cuda_fp16.h>
#include <cstdint>

#define BN 128
#define HN 512
#define EN 256
#define VN 50000
#define SN 200
#define KT 1792     // 3H + E
#define GIN 1280    // 2H + E

// ---------------- device scratch (allocation-free rule: __device__ globals) ----
__device__ float g_u2p[32 * 1024];
__device__ float g_u2[1024];
__device__ float g_to[BN * KT];               // to_out = [h_new | context | emb_x]
__device__ __align__(16) __half g_ahi[BN * KT];
__device__ __align__(16) __half g_alo[BN * KT];

#define SWZ128(o) ((o) ^ (((o) >> 3) & 0x70))

__device__ __forceinline__ uint32_t smem_cast(const void* p) {
    return (uint32_t)__cvta_generic_to_shared(p);
}

#define CP_ASYNC16(s, g) asm volatile("cp.async.cg.shared.global [%0], [%1], 16;" :: "r"(s), "l"(g))
#define CP_COMMIT()      asm volatile("cp.async.commit_group;" ::: "memory")
#define CP_WAIT_ALL()    asm volatile("cp.async.wait_all;" ::: "memory")
#define CP_WAIT1()       asm volatile("cp.async.wait_group 1;" ::: "memory")
#define CP_WAIT0()       asm volatile("cp.async.wait_group 0;" ::: "memory")

// ---------------- kernel 1: emb gather into to_out[:, 1536:1792] ---------------
__global__ void k_emb(const int* __restrict__ x, const float* __restrict__ emb) {
    int b = blockIdx.x;
    g_to[b * KT + 1536 + threadIdx.x] = emb[(size_t)x[b] * EN + threadIdx.x];
}

// ---------------- kernel 2/3: u2 = attn_w[:, H:3H].T @ v (partial + reduce) ----
__global__ void k_u2p(const float* __restrict__ aw, const float* __restrict__ v) {
    int g = blockIdx.x;  // h-range [g*16, g*16+16)
    for (int jj = 0; jj < 4; jj++) {
        int j = threadIdx.x + jj * 256;
        float acc = 0.f;
#pragma unroll
        for (int h = 0; h < 16; h++) {
            int hh = g * 16 + h;
            acc += v[hh] * aw[(size_t)hh * 1536 + 512 + j];
        }
        g_u2p[g * 1024 + j] = acc;
    }
}

__global__ void k_u2r() {
    int j = blockIdx.x * 256 + threadIdx.x;
    float s = 0.f;
#pragma unroll
    for (int g = 0; g < 32; g++) s += g_u2p[g * 1024 + j];
    g_u2[j] = s;
}

// ---------------- kernel 4: attention, single DRAM pass (online softmax) -------
#define ATTN_SMEM ((2 * 16 * 1024 + 1024) * 4)

__global__ __launch_bounds__(256) void k_attn(const float* __restrict__ enc) {
    extern __shared__ float sm[];
    float* s_enc = sm;                    // [2][16*1024]
    float* s_u2 = sm + 2 * 16 * 1024;     // [1024]
    __shared__ float s_sc[16];
    int tid = threadIdx.x, wid = tid >> 5, lid = tid & 31;
    int b = blockIdx.x;
    const float* base = enc + (size_t)b * SN * 1024;

    for (int i = tid; i < 1024; i += 256) s_u2[i] = g_u2[i];

    {
        uint32_t sa = smem_cast(s_enc);
        for (int u = tid; u < 16 * 256; u += 256)
            CP_ASYNC16(sa + u * 16, (const char*)base + (size_t)u * 16);
        CP_COMMIT();
    }

    float m = -1e30f, sum = 0.f;
    float c0 = 0.f, c1 = 0.f, c2 = 0.f, c3 = 0.f;
    const int NT = 13;  // 12 x 16 + 8
    for (int t = 0; t < NT; t++) {
        int nr = (t == NT - 1) ? (SN - 16 * (NT - 1)) : 16;
        float* buf = s_enc + (t & 1) * 16 * 1024;
        if (t + 1 < NT) {
            int nr2 = (t + 1 == NT - 1) ? (SN - 16 * (NT - 1)) : 16;
            uint32_t sa = smem_cast(s_enc + ((t + 1) & 1) * 16 * 1024);
            const char* g = (const char*)(base + (size_t)(t + 1) * 16 * 1024);
            for (int u = tid; u < nr2 * 256; u += 256)
                CP_ASYNC16(sa + u * 16, g + (size_t)u * 16);
            CP_COMMIT();
            CP_WAIT1();
        } else {
            CP_WAIT0();
        }
        __syncthreads();

        const float4* u24 = (const float4*)s_u2;
        for (int j = wid; j < nr; j += 8) {
            const float4* row = (const float4*)(buf + j * 1024);
            float acc = 0.f;
#pragma unroll 4
            for (int q = lid; q < 256; q += 32) {
                float4 e = row[q], u = u24[q];
                acc += e.x * u.x + e.y * u.y + e.z * u.z + e.w * u.w;
            }
#pragma unroll
            for (int o = 16; o; o >>= 1) acc += __shfl_xor_sync(0xffffffffu, acc, o);
            if (lid == 0) s_sc[j] = acc;
        }
        __syncthreads();

        float nm = m;
        for (int j = 0; j < nr; j++) nm = fmaxf(nm, s_sc[j]);
        float scl = expf(m - nm);
        c0 *= scl; c1 *= scl; c2 *= scl; c3 *= scl; sum *= scl;
        for (int j = 0; j < nr; j++) {
            float p = expf(s_sc[j] - nm);
            sum += p;
            const float* r = buf + j * 1024;
            c0 += p * r[tid];
            c1 += p * r[tid + 256];
            c2 += p * r[tid + 512];
            c3 += p * r[tid + 768];
        }
        m = nm;
        __syncthreads();
    }

    float inv = 1.0f / sum;
    g_to[b * KT + 512 + tid]       = c0 * inv;
    g_to[b * KT + 512 + tid + 256] = c1 * inv;
    g_to[b * KT + 512 + tid + 512] = c2 * inv;
    g_to[b * KT + 512 + tid + 768] = c3 * inv;
}

// ---------------- kernel 5: GRU cell, 8 b per CTA (weight reuse x8) ------------
#define GRU_SMEM ((8 * GIN + 8 * HN) * 4)

__global__ __launch_bounds__(256) void k_gru(
    const float* __restrict__ hid, const float* __restrict__ wih,
    const float* __restrict__ whh, const float* __restrict__ bih,
    const float* __restrict__ bhh, float* __restrict__ outh) {
    extern __shared__ float sm[];
    float* s_tg = sm;               // [8][1280]
    float* s_h0 = sm + 8 * GIN;     // [8][512]
    int tid = threadIdx.x, w = tid >> 5, lid = tid & 31;
    int bg = blockIdx.x >> 3;
    int kq = blockIdx.x & 7;
    int b0 = bg * 8;

    for (int i = tid; i < 8 * GIN; i += 256) {
        int bb = i / GIN, ii = i - bb * GIN;
        int b = b0 + bb;
        float v = (ii < EN) ? g_to[b * KT + 1536 + ii] : g_to[b * KT + 512 + (ii - EN)];
        s_tg[i] = fmaxf(v, 0.f);
    }
    for (int i = tid; i < 8 * HN; i += 256) {
        int bb = i >> 9, ii = i & 511;
        s_h0[i] = hid[(b0 + bb) * HN + ii];
    }
    __syncthreads();

    for (int kk = 0; kk < 8; kk++) {
        int k = kq * 64 + w * 8 + kk;
        float ar[8], az[8], an[8], ahn[8];
#pragma unroll
        for (int bb = 0; bb < 8; bb++) { ar[bb] = az[bb] = an[bb] = ahn[bb] = 0.f; }

        const float4* wr = (const float4*)(wih + (size_t)k * GIN);
        const float4* wz = (const float4*)(wih + (size_t)(k + 512) * GIN);
        const float4* wn = (const float4*)(wih + (size_t)(k + 1024) * GIN);
        for (int j = lid; j < GIN / 4; j += 32) {
            float4 A = wr[j], B = wz[j], C = wn[j];
#pragma unroll
            for (int bb = 0; bb < 8; bb++) {
                float4 t = ((const float4*)(s_tg + bb * GIN))[j];
                ar[bb] += A.x * t.x + A.y * t.y + A.z * t.z + A.w * t.w;
                az[bb] += B.x * t.x + B.y * t.y + B.z * t.z + B.w * t.w;
                an[bb] += C.x * t.x + C.y * t.y + C.z * t.z + C.w * t.w;
            }
        }
        const float4* vr = (const float4*)(whh + (size_t)k * HN);
        const float4* vz = (const float4*)(whh + (size_t)(k + 512) * HN);
        const float4* vn = (const float4*)(whh + (size_t)(k + 1024) * HN);
        for (int j = lid; j < HN / 4; j += 32) {
            float4 A = vr[j], B = vz[j], C = vn[j];
#pragma unroll
            for (int bb = 0; bb < 8; bb++) {
                float4 t = ((const float4*)(s_h0 + bb * HN))[j];
                ar[bb] += A.x * t.x + A.y * t.y + A.z * t.z + A.w * t.w;
                az[bb] += B.x * t.x + B.y * t.y + B.z * t.z + B.w * t.w;
                ahn[bb] += C.x * t.x + C.y * t.y + C.z * t.z + C.w * t.w;
            }
        }
#pragma unroll
        for (int o = 16; o; o >>= 1) {
#pragma unroll
            for (int bb = 0; bb < 8; bb++) {
                ar[bb] += __shfl_xor_sync(0xffffffffu, ar[bb], o);
                az[bb] += __shfl_xor_sync(0xffffffffu, az[bb], o);
                an[bb] += __shfl_xor_sync(0xffffffffu, an[bb], o);
                ahn[bb] += __shfl_xor_sync(0xffffffffu, ahn[bb], o);
            }
        }
        if (lid == 0) {
            float br_ = bih[k] + bhh[k];
            float bz_ = bih[k + 512] + bhh[k + 512];
            float bin = bih[k + 1024], bhn = bhh[k + 1024];
#pragma unroll
            for (int bb = 0; bb < 8; bb++) {
                float r = 1.f / (1.f + expf(-(ar[bb] + br_)));
                float z = 1.f / (1.f + expf(-(az[bb] + bz_)));
                float n = tanhf(an[bb] + bin + r * (ahn[bb] + bhn));
                float h = (1.f - z) * n + z * s_h0[bb * HN + k];
                g_to[(b0 + bb) * KT + k] = h;
                outh[(b0 + bb) * HN + k] = h;
            }
        }
    }
}

// ---------------- kernel 6: split to_out into fp16 hi/lo -----------------------
__global__ void k_conv() {
    int b = blockIdx.x;
    for (int i = threadIdx.x; i < KT; i += 256) {
        float xv = g_to[b * KT + i];
        __half hx = __float2half_rn(xv);
        g_ahi[b * KT + i] = hx;
        g_alo[b * KT + i] = __float2half_rn(xv - __half2float(hx));
    }
}

// ---------------- kernel 7: logits, split-fp16 mma.sync, chunk-pipelined -------
// C[128, 64-tile of V] = Ahi@Whi^T + Alo@Whi^T   (fp32 accum)
// Full chunk (A hi/lo 2x16KB + W fp32 16KB) double-buffered via cp.async:
// prefetch distance = 1 chunk (~2.5k cyc) >> DRAM latency. W read via LDS.

#define ABYTES 16384
#define WROWF  68                      // 64 + 4 pad floats (16B-aligned rows)
#define WBYTES (64 * WROWF * 4)        // 17408
#define SSTG   (2 * ABYTES + WBYTES)   // 50176 per stage
#define LOG_SMEM (2 * SSTG)            // 100352

#define NCHUNK 28

__device__ __forceinline__ void mma16816(float* c, const uint32_t* a, uint32_t b0, uint32_t b1) {
    asm volatile(
        "mma.sync.aligned.m16n8k16.row.col.f32.f16.f16.f32 "
        "{%0,%1,%2,%3}, {%4,%5,%6,%7}, {%8,%9}, {%0,%1,%2,%3};"
        : "+f"(c[0]), "+f"(c[1]), "+f"(c[2]), "+f"(c[3])
        : "r"(a[0]), "r"(a[1]), "r"(a[2]), "r"(a[3]), "r"(b0), "r"(b1));
}

__device__ __forceinline__ void stage_chunk(int ch, uint32_t sbase, int tid,
                                            const char* ah, const char* al,
                                            const float* W, int v0) {
    uint32_t sa_hi = sbase;
    uint32_t sa_lo = sbase + ABYTES;
    uint32_t sa_w  = sbase + 2 * ABYTES;
#pragma unroll
    for (int i = 0; i < 4; i++) {
        int q = tid + i * 256;
        int row = q >> 3, seg = q & 7;
        uint32_t sw = SWZ128((uint32_t)(row * 128 + seg * 16));
        CP_ASYNC16(sa_hi + sw, ah + (size_t)ch * 128 + (size_t)row * (KT * 2) + seg * 16);
        CP_ASYNC16(sa_lo + sw, al + (size_t)ch * 128 + (size_t)row * (KT * 2) + seg * 16);
    }
#pragma unroll
    for (int i = 0; i < 4; i++) {
        int u = tid + i * 256;
        int row = u >> 4, seg = u & 15;
        int vr = v0 + row;
        if (vr >= VN) vr = VN - 1;     // clamp; outputs masked in epilogue
        CP_ASYNC16(sa_w + row * (WROWF * 4) + seg * 16,
                   (const char*)(W + (size_t)vr * KT + ch * 64) + seg * 16);
    }
    CP_COMMIT();
}

__global__ __launch_bounds__(256, 2) void k_logits(const float* __restrict__ W,
                                                   const float* __restrict__ bias,
                                                   float* __restrict__ out) {
    extern __shared__ char smem[];
    int tid = threadIdx.x, wid = tid >> 5, lid = tid & 31;
    int v0 = blockIdx.x * 64;
    int warpM = (wid & 1) * 64;
    int warpN = (wid >> 1) * 16;
    int lr = lid >> 2, lq = lid & 3;
    int lrow = lid & 15;
    int lcolh = (lid >> 4) * 16;

    uint32_t sb = smem_cast(smem);
    const char* ah = (const char*)g_ahi;
    const char* al = (const char*)g_alo;

    float c[4][2][4];
#pragma unroll
    for (int mt = 0; mt < 4; mt++)
#pragma unroll
        for (int nt = 0; nt < 2; nt++)
#pragma unroll
            for (int j = 0; j < 4; j++) c[mt][nt][j] = 0.f;

    stage_chunk(0, sb, tid, ah, al, W, v0);
    stage_chunk(1, sb + SSTG, tid, ah, al, W, v0);

    for (int ch = 0; ch < NCHUNK; ch++) {
        if (ch == NCHUNK - 1) { CP_WAIT0(); } else { CP_WAIT1(); }
        __syncthreads();

        uint32_t sbuf = sb + (uint32_t)(ch & 1) * SSTG;
        uint32_t sa_hi = sbuf;
        uint32_t sa_lo = sbuf + ABYTES;
        const float* sW = (const float*)(smem + (ch & 1) * SSTG + 2 * ABYTES);

#pragma unroll
        for (int s = 0; s < 4; s++) {
            uint32_t ahi[4][4], alo[4][4];
#pragma unroll
            for (int mt = 0; mt < 4; mt++) {
                int row = warpM + mt * 16 + lrow;
                uint32_t off = SWZ128((uint32_t)(row * 128 + s * 32 + lcolh));
                asm volatile("ldmatrix.sync.aligned.m8n8.x4.shared.b16 {%0,%1,%2,%3}, [%4];"
                             : "=r"(ahi[mt][0]), "=r"(ahi[mt][1]), "=r"(ahi[mt][2]), "=r"(ahi[mt][3])
                             : "r"(sa_hi + off));
                asm volatile("ldmatrix.sync.aligned.m8n8.x4.shared.b16 {%0,%1,%2,%3}, [%4];"
                             : "=r"(alo[mt][0]), "=r"(alo[mt][1]), "=r"(alo[mt][2]), "=r"(alo[mt][3])
                             : "r"(sa_lo + off));
            }
#pragma unroll
            for (int nt = 0; nt < 2; nt++) {
                const float* wr = sW + (warpN + nt * 8 + lr) * WROWF + s * 16 + lq * 2;
                float2 w0 = *(const float2*)wr;
                float2 w1 = *(const float2*)(wr + 8);
                __half2 h0 = __floats2half2_rn(w0.x, w0.y);  // .x -> low half
                __half2 h1 = __floats2half2_rn(w1.x, w1.y);
                uint32_t bh0 = *(uint32_t*)&h0, bh1 = *(uint32_t*)&h1;
#pragma unroll
                for (int mt = 0; mt < 4; mt++) mma16816(c[mt][nt], ahi[mt], bh0, bh1);
#pragma unroll
                for (int mt = 0; mt < 4; mt++) mma16816(c[mt][nt], alo[mt], bh0, bh1);
            }
        }
        __syncthreads();
        if (ch + 2 < NCHUNK)
            stage_chunk(ch + 2, sbuf, tid, ah, al, W, v0);
    }

    // epilogue: add bias, store
#pragma unroll
    for (int nt = 0; nt < 2; nt++) {
        int col = v0 + warpN + nt * 8 + lq * 2;
        float b0 = 0.f, b1 = 0.f;
        if (col < VN) b0 = bias[col];
        if (col + 1 < VN) b1 = bias[col + 1];
#pragma unroll
        for (int mt = 0; mt < 4; mt++) {
            int row = warpM + mt * 16 + lr;
            if (col < VN) {
                out[(size_t)row * VN + col]       = c[mt][nt][0] + b0;
                out[(size_t)(row + 8) * VN + col] = c[mt][nt][2] + b0;
            }
            if (col + 1 < VN) {
                out[(size_t)row * VN + col + 1]       = c[mt][nt][1] + b1;
                out[(size_t)(row + 8) * VN + col + 1] = c[mt][nt][3] + b1;
            }
        }
    }
}

// ---------------- launch --------------------------------------------------------
extern "C" void kernel_launch(void* const* d_in, const int* in_sizes, int n_in,
                              void* d_out, int out_size) {
    const int*   x      = (const int*)d_in[0];
    const float* hidden = (const float*)d_in[1];
    const float* enc    = (const float*)d_in[2];
    const float* emb    = (const float*)d_in[3];
    const float* attn_w = (const float*)d_in[4];
    // d_in[5] = attn_b (softmax-invariant, unused)
    const float* v      = (const float*)d_in[6];
    const float* w_ih   = (const float*)d_in[7];
    const float* w_hh   = (const float*)d_in[8];
    const float* b_ih   = (const float*)d_in[9];
    const float* b_hh   = (const float*)d_in[10];
    const float* out_w  = (const float*)d_in[11];
    const float* out_b  = (const float*)d_in[12];
    float* out = (float*)d_out;

    cudaFuncSetAttribute(k_attn, cudaFuncAttributeMaxDynamicSharedMemorySize, ATTN_SMEM);
    cudaFuncSetAttribute(k_gru, cudaFuncAttributeMaxDynamicSharedMemorySize, GRU_SMEM);
    cudaFuncSetAttribute(k_logits, cudaFuncAttributeMaxDynamicSharedMemorySize, LOG_SMEM);

    k_emb<<<BN, 256>>>(x, emb);
    k_u2p<<<32, 256>>>(attn_w, v);
    k_u2r<<<4, 256>>>();
    k_attn<<<BN, 256, ATTN_SMEM>>>(enc);
    k_gru<<<BN, 256, GRU_SMEM>>>(hidden, w_ih, w_hh, b_ih, b_hh, out + (size_t)BN * VN);
    k_conv<<<BN, 256>>>();

    k_logits<<<(VN + 63) / 64, 256, LOG_SMEM>>>(out_w, out_b, out);
}